// round 3
// baseline (speedup 1.0000x reference)
#include <cuda_runtime.h>

#define BGRAPH 64
#define HID    128
#define NCLS   10
#define NMLP   16     // last 16 blocks each handle 4 graph rows

// Persistent scratch (allocation-free rule: __device__ globals)
// layout: [0,64)   sum_comp
//         [64,128) sum_port_col0
//         [128,192)sum_port_col1
//         [192,256)sum_net
//         [256,320)cnt_comp
//         [320,384)cnt_port
//         [384,448)cnt_net
__device__ float g_acc[7 * BGRAPH];
__device__ int   g_ctr;    // pooling-done counter
__device__ int   g_ctr2;   // mlp-read-done counter

__device__ __forceinline__ float wred(float v) {
#pragma unroll
    for (int o = 16; o; o >>= 1) v += __shfl_xor_sync(0xffffffffu, v, o);
    return v;
}

__global__ void __launch_bounds__(256, 8)
k_fused(const float* __restrict__ hc, const float* __restrict__ hp,
        const float* __restrict__ hn,
        const int* __restrict__ gc, const int* __restrict__ gp,
        const int* __restrict__ gn,
        int nc, int np, int nn,
        const float* __restrict__ Wc1, const float* __restrict__ bc1,
        const float* __restrict__ Wc2, const float* __restrict__ bc2,
        const float* __restrict__ Wc3, const float* __restrict__ bc3,
        float* __restrict__ out) {
    const int t = threadIdx.x;

    // ===================== phase 1: pooling (all blocks) =====================
    {
        int idx = blockIdx.x * blockDim.x + t;
        int region = 3;                        // 3 == out of range
        float v0 = 0.f, v1 = 0.f;
        int gid = -1;

        if (idx < nc) {
            region = 0; v0 = hc[idx]; gid = gc[idx];
        } else if (idx < nc + np) {
            int i = idx - nc;
            region = 1;
            float2 p = reinterpret_cast<const float2*>(hp)[i];
            v0 = p.x; v1 = p.y;
            gid = gp[i];
        } else if (idx < nc + np + nn) {
            int i = idx - nc - np;
            region = 2; v0 = hn[i]; gid = gn[i];
        }

        const unsigned full = 0xffffffffu;
        int r0 = __shfl_sync(full, region, 0);
        int g0 = __shfl_sync(full, gid, 0);
        bool uni = __all_sync(full, (region == r0) && (gid == g0));

        if (uni) {
            if (r0 != 3) {                     // gid-uniform warp (common, sorted gids)
                float s0 = wred(v0);
                if (r0 == 1) {
                    float s1 = wred(v1);
                    if ((t & 31) == 0) {
                        atomicAdd(&g_acc[64  + g0], s0);
                        atomicAdd(&g_acc[128 + g0], s1);
                        atomicAdd(&g_acc[320 + g0], 32.f);
                    }
                } else {
                    int base  = (r0 == 0) ? 0   : 192;
                    int basec = (r0 == 0) ? 256 : 384;
                    if ((t & 31) == 0) {
                        atomicAdd(&g_acc[base  + g0], s0);
                        atomicAdd(&g_acc[basec + g0], 32.f);
                    }
                }
            }
        } else {
            if (region == 0) {
                atomicAdd(&g_acc[gid], v0);
                atomicAdd(&g_acc[256 + gid], 1.f);
            } else if (region == 1) {
                atomicAdd(&g_acc[64  + gid], v0);
                atomicAdd(&g_acc[128 + gid], v1);
                atomicAdd(&g_acc[320 + gid], 1.f);
            } else if (region == 2) {
                atomicAdd(&g_acc[192 + gid], v0);
                atomicAdd(&g_acc[384 + gid], 1.f);
            }
        }
    }

    // ============== election: last NMLP finishers run the MLP ==============
    __shared__ int s_done;
    __syncthreads();                           // all warps' atomics issued
    if (t == 0) {
        __threadfence();                       // make g_acc updates visible
        s_done = atomicAdd(&g_ctr, 1);
    }
    __syncthreads();

    const int npool = gridDim.x;
    const int which = s_done - (npool - NMLP);
    if (which < 0) return;                     // not elected

    // wait for every block's pooling contribution
    if (t == 0) {
        while (atomicAdd(&g_ctr, 0) < npool) __nanosleep(40);
    }
    __syncthreads();

    // ===================== phase 2: MLP, rows [which*4, which*4+4) ==========
    __shared__ float hg[4][4];
    __shared__ float h1s[4][HID];
    __shared__ float h2s[4][HID];
    __shared__ int   s_r2;

    if (t < 4) {
        int gi = which * 4 + t;
        float c0 = fmaxf(__ldcg(&g_acc[256 + gi]), 1.f);
        float c1 = fmaxf(__ldcg(&g_acc[320 + gi]), 1.f);
        float c2 = fmaxf(__ldcg(&g_acc[384 + gi]), 1.f);
        hg[t][0] = __ldcg(&g_acc[gi])        / c0;
        hg[t][1] = __ldcg(&g_acc[64  + gi])  / c1;
        hg[t][2] = __ldcg(&g_acc[128 + gi])  / c1;
        hg[t][3] = __ldcg(&g_acc[192 + gi])  / c2;
    }
    __syncthreads();                           // g_acc reads of this block done
    if (t == 0) s_r2 = atomicAdd(&g_ctr2, 1); // safe: reads complete

    // ---- layer 1: h1 = relu(hg @ Wc1 + bc1) for 4 rows ----
    {
        int j    = t & (HID - 1);
        int half = t >> 7;                     // 0..1 -> rows {2h, 2h+1}
        float b  = bc1[j];
        float w0 = Wc1[j];
        float w1 = Wc1[HID + j];
        float w2 = Wc1[2 * HID + j];
        float w3 = Wc1[3 * HID + j];
#pragma unroll
        for (int rr = 0; rr < 2; rr++) {
            int r = half * 2 + rr;
            float a = b + hg[r][0] * w0 + hg[r][1] * w1 + hg[r][2] * w2 + hg[r][3] * w3;
            h1s[r][j] = fmaxf(a, 0.f);
        }
    }
    __syncthreads();

    // ---- layer 2: h2 = relu(h1 @ Wc2 + bc2), 4x128, 2 rows per thread ----
    {
        int col = t & (HID - 1);
        int rp  = t >> 7;                      // 0..1 -> rows {rp, rp+2}
        float a0 = bc2[col], a1 = a0;
#pragma unroll 8
        for (int k = 0; k < HID; k++) {
            float w = Wc2[k * HID + col];
            a0 += h1s[rp][k]     * w;
            a1 += h1s[rp + 2][k] * w;
        }
        h2s[rp][col]     = fmaxf(a0, 0.f);
        h2s[rp + 2][col] = fmaxf(a1, 0.f);
    }
    __syncthreads();

    // ---- layer 3: out rows = h2 @ Wc3 + bc3, 4x10, direct store ----
    if (t < 4 * NCLS) {
        int r = t / NCLS, c = t % NCLS;
        float acc = bc3[c];
#pragma unroll 8
        for (int k = 0; k < HID; k++)
            acc += h2s[r][k] * Wc3[k * NCLS + c];
        out[(which * 4 + r) * NCLS + c] = acc;
    }

    // ---- cleanup for next graph replay: last MLP block resets state ----
    __syncthreads();
    if (s_r2 == NMLP - 1) {                    // every block has read g_acc
        for (int i = t; i < 7 * BGRAPH; i += 256) g_acc[i] = 0.f;
        if (t == 0) { g_ctr = 0; g_ctr2 = 0; }
    }
}

// ---------------------------------------------------------------------------
// launch: one fused kernel, one graph node
// ---------------------------------------------------------------------------
extern "C" void kernel_launch(void* const* d_in, const int* in_sizes, int n_in,
                              void* d_out, int out_size) {
    const float* h_comp = (const float*)d_in[0];
    const float* h_port = (const float*)d_in[1];
    const float* h_net  = (const float*)d_in[2];
    // d_in[3..6]: edge arrays — dead code in the reference, never read
    const int* gid_comp = (const int*)d_in[7];
    const int* gid_port = (const int*)d_in[8];
    const int* gid_net  = (const int*)d_in[9];
    // d_in[10..21]: GraphConv weights — dead code in the reference, never read
    const float* Wc1 = (const float*)d_in[22];
    const float* bc1 = (const float*)d_in[23];
    const float* Wc2 = (const float*)d_in[24];
    const float* bc2 = (const float*)d_in[25];
    const float* Wc3 = (const float*)d_in[26];
    const float* bc3 = (const float*)d_in[27];

    float* out = (float*)d_out;

    int nc = in_sizes[0];
    int np = in_sizes[1] / 2;
    int nn = in_sizes[2];
    int total = nc + np + nn;

    int threads = 256;
    int blocks = (total + threads - 1) / threads;   // 2540 >> NMLP

    k_fused<<<blocks, threads>>>(h_comp, h_port, h_net,
                                 gid_comp, gid_port, gid_net,
                                 nc, np, nn,
                                 Wc1, bc1, Wc2, bc2, Wc3, bc3,
                                 out);
}